// round 13
// baseline (speedup 1.0000x reference)
#include <cuda_runtime.h>
#include <cstdint>
#include <math.h>

#define M_BATCH 2048
#define T_SEQ   64
#define IN_F    16
#define H_DIM   256
#define G_DIM   1024
#define NCOMP   64
#define OUT_DIM 192
#define NPOS    (M_BATCH * T_SEQ)   // 131072

// ---------------- scratch (device globals; no runtime allocation) -------------
__device__ float g_Hbuf[(size_t)NPOS * H_DIM];     // 134 MB
__device__ float g_gates[(size_t)M_BATCH * G_DIM]; // 8 MB
__device__ float g_h[M_BATCH * H_DIM];             // 2 MB
__device__ float g_c[M_BATCH * H_DIM];             // 2 MB
__device__ float g_y[(size_t)NPOS * OUT_DIM];      // 100 MB
__device__ int   g_mode;                           // PRNG scheme: 0=classic, 1=part, 2=part-swapped

// ---------------- JAX threefry2x32 (20 rounds) --------------------------------
__host__ __device__ __forceinline__ void tf2x32(uint32_t k0, uint32_t k1,
                                                uint32_t x0, uint32_t x1,
                                                uint32_t &o0, uint32_t &o1)
{
    uint32_t ks2 = k0 ^ k1 ^ 0x1BD11BDAu;
    x0 += k0; x1 += k1;
#define TF_R(r) { x0 += x1; x1 = (x1 << (r)) | (x1 >> (32 - (r))); x1 ^= x0; }
    TF_R(13) TF_R(15) TF_R(26) TF_R(6)
    x0 += k1;  x1 += ks2 + 1u;
    TF_R(17) TF_R(29) TF_R(16) TF_R(24)
    x0 += ks2; x1 += k0 + 2u;
    TF_R(13) TF_R(15) TF_R(26) TF_R(6)
    x0 += k0;  x1 += k1 + 3u;
    TF_R(17) TF_R(29) TF_R(16) TF_R(24)
    x0 += k1;  x1 += ks2 + 4u;
    TF_R(13) TF_R(15) TF_R(26) TF_R(6)
    x0 += ks2; x1 += k0 + 5u;
#undef TF_R
    o0 = x0; o1 = x1;
}

// classic JAX random_bits: odd/even half pairing over a draw of 2*half elements
__device__ __forceinline__ uint32_t bits_classic(uint32_t j, uint32_t half,
                                                 uint32_t ka, uint32_t kb) {
    uint32_t o0, o1;
    if (j < half) { tf2x32(ka, kb, j, j + half, o0, o1); return o0; }
    else          { tf2x32(ka, kb, j - half, j, o0, o1); return o1; }
}

// partitionable JAX random_bits (32-bit): counter = (hi=0, lo=j), fold = out0^out1
__device__ __forceinline__ uint32_t bits_part(uint32_t j, uint32_t ka, uint32_t kb) {
    uint32_t o0, o1;
    tf2x32(ka, kb, 0u, j, o0, o1);
    return o0 ^ o1;
}

// bits -> [0,1) float, JAX style
__device__ __forceinline__ float bits_to_unit(uint32_t bits) {
    return __uint_as_float((bits >> 9) | 0x3f800000u) - 1.0f;
}

// XLA ErfInv f32 (Giles polynomial)
__device__ __forceinline__ float erfinv32(float x) {
    float w = -log1pf(-x * x);
    float p;
    if (w < 5.0f) {
        w = w - 2.5f;
        p = 2.81022636e-08f;
        p = fmaf(p, w, 3.43273939e-07f);
        p = fmaf(p, w, -3.5233877e-06f);
        p = fmaf(p, w, -4.39150654e-06f);
        p = fmaf(p, w, 0.00021858087f);
        p = fmaf(p, w, -0.00125372503f);
        p = fmaf(p, w, -0.00417768164f);
        p = fmaf(p, w, 0.246640727f);
        p = fmaf(p, w, 1.50140941f);
    } else {
        w = sqrtf(w) - 3.0f;
        p = -0.000200214257f;
        p = fmaf(p, w, 0.000100950558f);
        p = fmaf(p, w, 0.00134934322f);
        p = fmaf(p, w, -0.00367342844f);
        p = fmaf(p, w, 0.00573950773f);
        p = fmaf(p, w, -0.0076224613f);
        p = fmaf(p, w, 0.00943887047f);
        p = fmaf(p, w, 1.00167406f);
        p = fmaf(p, w, 2.83297682f);
    }
    return p * x;
}

// standard normal from raw threefry bits (JAX: uniform(-0.99999994, 1) -> sqrt2*erfinv)
__device__ __forceinline__ float normal_from_bits(uint32_t bits) {
    float f = bits_to_unit(bits);
    float u = fmaxf(-0.99999994f, fmaf(f, 1.99999994f, -0.99999994f));
    return 1.41421356f * erfinv32(u);
}

// Gumbel from raw bits: -log(-log(uniform(tiny,1)))
__device__ __forceinline__ float gumbel_from_bits(uint32_t bits) {
    float f = bits_to_unit(bits);
    float u = fmaxf(1.17549435e-38f, f);
    return -logf(-logf(u));
}

// XLA/Eigen f32 tanh rational approximation
__device__ __forceinline__ float tanh_xla(float x) {
    float ax = fabsf(x);
    if (ax < 0.0004f) return x;
    float xc = fminf(fmaxf(x, -7.90531110763549805f), 7.90531110763549805f);
    float x2 = xc * xc;
    float p = -2.76076847742355e-16f;
    p = fmaf(p, x2, 2.00018790482477e-13f);
    p = fmaf(p, x2, -8.60467152213735e-11f);
    p = fmaf(p, x2, 5.12229709037114e-08f);
    p = fmaf(p, x2, 1.48572235717979e-05f);
    p = fmaf(p, x2, 6.37261928875436e-04f);
    p = fmaf(p, x2, 4.89352455891786e-03f);
    p = xc * p;
    float q = 1.19825839466702e-06f;
    q = fmaf(q, x2, 1.18534705686654e-04f);
    q = fmaf(q, x2, 2.26843463243900e-03f);
    q = fmaf(q, x2, 4.89352518554385e-03f);
    return p / q;
}

__device__ __forceinline__ float sigm(float x) {   // XLA logistic expansion
    return fmaf(0.5f, tanh_xla(0.5f * x), 0.5f);
}

// ---------------- PRNG scheme detection ----------------------------------------
// setup_inputs used key(0): ks = split(key(0), 12); z = normal(ks[0], (2048,64,16)).
// Predict z[0..4) under each candidate scheme; pick the closest. Pure function of
// the input data -> deterministic across calls.
__global__ void detect_mode(const float* __restrict__ z,
                            uint32_t ca, uint32_t cb,    // ks[0] classic
                            uint32_t pa, uint32_t pb)    // tf(0,0;0,0) outputs (o0,o1)
{
    if (threadIdx.x != 0 || blockIdx.x != 0) return;
    const uint32_t HALF_Z = 1048576u;  // 2048*64*16 / 2
    float d0 = 0.0f, d1 = 0.0f, d2 = 0.0f;
    for (uint32_t j = 0; j < 4; j++) {
        float zc = normal_from_bits(bits_classic(j, HALF_Z, ca, cb));
        float z1 = normal_from_bits(bits_part(j, pa, pb));   // key stacked (o0,o1)
        float z2 = normal_from_bits(bits_part(j, pb, pa));   // key stacked (o1,o0)
        float za = z[j];
        d0 += fabsf(za - zc);
        d1 += fabsf(za - z1);
        d2 += fabsf(za - z2);
    }
    int m = 0; float dbest = d0;
    if (d1 < dbest) { m = 1; dbest = d1; }
    if (d2 < dbest) { m = 2; }
    g_mode = m;
}

// ---------------- init ---------------------------------------------------------
__global__ void zero_hc() {
    int i = blockIdx.x * blockDim.x + threadIdx.x;
    if (i < M_BATCH * H_DIM) { g_h[i] = 0.0f; g_c[i] = 0.0f; }
}

// ---------------- gates GEMM: gates = [x_t,h] @ [Wih,Whh]^T + bih + bhh --------
// BM=64, BN=128, BK=16, 256 threads, 4x8 per-thread microtile. 256 blocks.
__global__ void gates_gemm(const float* __restrict__ X, int F, int t,
                           const float* __restrict__ Wih,
                           const float* __restrict__ Whh,
                           const float* __restrict__ bih,
                           const float* __restrict__ bhh)
{
    __shared__ float As[16][68];
    __shared__ float Bs[16][132];
    const float* Xp = (F == IN_F) ? X : g_Hbuf;

    int tid = threadIdx.x;
    int m0 = blockIdx.y * 64;
    int n0 = blockIdx.x * 128;
    int tx = tid & 15, ty = tid >> 4;

    float acc[4][8];
#pragma unroll
    for (int r = 0; r < 4; r++)
#pragma unroll
        for (int c = 0; c < 8; c++) acc[r][c] = 0.0f;

    int K = F + H_DIM;
    for (int k0 = 0; k0 < K; k0 += 16) {
        bool isX = (k0 < F);
        {
            int ml = tid >> 2;
            int c4 = (tid & 3) * 4;
            int mg = m0 + ml;
            float4 v;
            if (isX) v = *reinterpret_cast<const float4*>(Xp + ((size_t)mg * T_SEQ + t) * F + (k0 + c4));
            else     v = *reinterpret_cast<const float4*>(g_h + (size_t)mg * H_DIM + (k0 - F + c4));
            As[c4 + 0][ml] = v.x; As[c4 + 1][ml] = v.y; As[c4 + 2][ml] = v.z; As[c4 + 3][ml] = v.w;
        }
#pragma unroll
        for (int i = 0; i < 2; i++) {
            int idx = tid + i * 256;
            int nl = idx >> 2;
            int c4 = (idx & 3) * 4;
            int ng = n0 + nl;
            float4 v;
            if (isX) v = *reinterpret_cast<const float4*>(Wih + (size_t)ng * F + (k0 + c4));
            else     v = *reinterpret_cast<const float4*>(Whh + (size_t)ng * H_DIM + (k0 - F + c4));
            Bs[c4 + 0][nl] = v.x; Bs[c4 + 1][nl] = v.y; Bs[c4 + 2][nl] = v.z; Bs[c4 + 3][nl] = v.w;
        }
        __syncthreads();
#pragma unroll
        for (int kk = 0; kk < 16; kk++) {
            float a[4], b[8];
            *reinterpret_cast<float4*>(&a[0]) = *reinterpret_cast<const float4*>(&As[kk][ty * 4]);
            *reinterpret_cast<float4*>(&b[0]) = *reinterpret_cast<const float4*>(&Bs[kk][tx * 8]);
            *reinterpret_cast<float4*>(&b[4]) = *reinterpret_cast<const float4*>(&Bs[kk][tx * 8 + 4]);
#pragma unroll
            for (int r = 0; r < 4; r++)
#pragma unroll
                for (int c = 0; c < 8; c++) acc[r][c] = fmaf(a[r], b[c], acc[r][c]);
        }
        __syncthreads();
    }
    float bb[8];
#pragma unroll
    for (int c = 0; c < 8; c++) {
        int ng = n0 + tx * 8 + c;
        bb[c] = bih[ng] + bhh[ng];
    }
#pragma unroll
    for (int r = 0; r < 4; r++) {
        int mg = m0 + ty * 4 + r;
        float* dst = g_gates + (size_t)mg * G_DIM + n0 + tx * 8;
        float4 v0 = make_float4(acc[r][0] + bb[0], acc[r][1] + bb[1], acc[r][2] + bb[2], acc[r][3] + bb[3]);
        float4 v1 = make_float4(acc[r][4] + bb[4], acc[r][5] + bb[5], acc[r][6] + bb[6], acc[r][7] + bb[7]);
        *reinterpret_cast<float4*>(dst) = v0;
        *reinterpret_cast<float4*>(dst + 4) = v1;
    }
}

// ---------------- LSTM pointwise update (float4-vectorized) --------------------
__global__ void lstm_point(int t) {
    int q = blockIdx.x * blockDim.x + threadIdx.x;
    int i = q * 4;
    int m = i >> 8;
    int j = i & 255;
    const float* gr = g_gates + (size_t)m * G_DIM;
    float4 ig = *reinterpret_cast<const float4*>(gr + j);
    float4 fg = *reinterpret_cast<const float4*>(gr + 256 + j);
    float4 gg = *reinterpret_cast<const float4*>(gr + 512 + j);
    float4 og = *reinterpret_cast<const float4*>(gr + 768 + j);
    float4 c  = *reinterpret_cast<const float4*>(g_c + i);
    float4 h;
    c.x = sigm(fg.x) * c.x + sigm(ig.x) * tanh_xla(gg.x);
    c.y = sigm(fg.y) * c.y + sigm(ig.y) * tanh_xla(gg.y);
    c.z = sigm(fg.z) * c.z + sigm(ig.z) * tanh_xla(gg.z);
    c.w = sigm(fg.w) * c.w + sigm(ig.w) * tanh_xla(gg.w);
    h.x = sigm(og.x) * tanh_xla(c.x);
    h.y = sigm(og.y) * tanh_xla(c.y);
    h.z = sigm(og.z) * tanh_xla(c.z);
    h.w = sigm(og.w) * tanh_xla(c.w);
    *reinterpret_cast<float4*>(g_c + i) = c;
    *reinterpret_cast<float4*>(g_h + i) = h;
    *reinterpret_cast<float4*>(g_Hbuf + ((size_t)m * T_SEQ + t) * H_DIM + j) = h;
}

// ---------------- FC GEMM: y = H1 @ fcW^T + fcb -------------------------------
__global__ void fc_gemm(const float* __restrict__ fcW, const float* __restrict__ fcb) {
    __shared__ float As[16][68];
    __shared__ float Bs[16][68];
    int tid = threadIdx.x;
    int m0 = blockIdx.y * 64;
    int n0 = blockIdx.x * 64;
    int tx = tid & 15, ty = tid >> 4;
    float acc[4][4];
#pragma unroll
    for (int r = 0; r < 4; r++)
#pragma unroll
        for (int c = 0; c < 4; c++) acc[r][c] = 0.0f;

    for (int k0 = 0; k0 < H_DIM; k0 += 16) {
        {
            int ml = tid >> 2, c4 = (tid & 3) * 4;
            float4 v = *reinterpret_cast<const float4*>(g_Hbuf + (size_t)(m0 + ml) * H_DIM + k0 + c4);
            As[c4 + 0][ml] = v.x; As[c4 + 1][ml] = v.y; As[c4 + 2][ml] = v.z; As[c4 + 3][ml] = v.w;
        }
        {
            int nl = tid >> 2, c4 = (tid & 3) * 4;
            float4 v = *reinterpret_cast<const float4*>(fcW + (size_t)(n0 + nl) * H_DIM + k0 + c4);
            Bs[c4 + 0][nl] = v.x; Bs[c4 + 1][nl] = v.y; Bs[c4 + 2][nl] = v.z; Bs[c4 + 3][nl] = v.w;
        }
        __syncthreads();
#pragma unroll
        for (int kk = 0; kk < 16; kk++) {
            float a[4], b[4];
            *reinterpret_cast<float4*>(a) = *reinterpret_cast<const float4*>(&As[kk][ty * 4]);
            *reinterpret_cast<float4*>(b) = *reinterpret_cast<const float4*>(&Bs[kk][tx * 4]);
#pragma unroll
            for (int r = 0; r < 4; r++)
#pragma unroll
                for (int c = 0; c < 4; c++) acc[r][c] = fmaf(a[r], b[c], acc[r][c]);
        }
        __syncthreads();
    }
#pragma unroll
    for (int r = 0; r < 4; r++) {
        int mg = m0 + ty * 4 + r;
        float* dst = g_y + (size_t)mg * OUT_DIM + n0 + tx * 4;
        float4 v = make_float4(acc[r][0] + fcb[n0 + tx * 4 + 0],
                               acc[r][1] + fcb[n0 + tx * 4 + 1],
                               acc[r][2] + fcb[n0 + tx * 4 + 2],
                               acc[r][3] + fcb[n0 + tx * 4 + 3]);
        *reinterpret_cast<float4*>(dst) = v;
    }
}

// ---------------- MDN head: softmax + Gumbel categorical + normal + prob ------
__global__ void mdn_kernel(float* __restrict__ out,
                           uint32_t k1ca, uint32_t k1cb, uint32_t k2ca, uint32_t k2cb,
                           uint32_t s1a,  uint32_t s1b,  uint32_t s2a,  uint32_t s2b,
                           float C32)
{
    int warp = (blockIdx.x * blockDim.x + threadIdx.x) >> 5;
    int lane = threadIdx.x & 31;
    if (warp >= NPOS) return;
    const float* y = g_y + (size_t)warp * OUT_DIM;

    int mode = g_mode;
    // select per-scheme key pairs (k1 = categorical/gumbel key, k2 = normal key)
    uint32_t ka, kb, na, nb;
    if (mode == 0)      { ka = k1ca; kb = k1cb; na = k2ca; nb = k2cb; }
    else if (mode == 1) { ka = s1a;  kb = s1b;  na = s2a;  nb = s2b;  }
    else                { ka = s1b;  kb = s1a;  na = s2b;  nb = s2a;  }

    float yg1 = y[lane], yg2 = y[lane + 32];
    float mx = fmaxf(yg1, yg2);
#pragma unroll
    for (int o = 16; o; o >>= 1) mx = fmaxf(mx, __shfl_xor_sync(0xffffffffu, mx, o));
    float e1 = expf(yg1 - mx), e2 = expf(yg2 - mx);
    float s = e1 + e2;
#pragma unroll
    for (int o = 16; o; o >>= 1) s += __shfl_xor_sync(0xffffffffu, s, o);
    float gam1 = e1 / s, gam2 = e2 / s;

    // gumbel draw over shape (2048,64,64); flat index of (pos=warp, comp)
    const uint32_t HALF_G = 4194304u;
    uint32_t j1 = (uint32_t)warp * 64u + (uint32_t)lane;
    uint32_t gb1, gb2;
    if (mode == 0) { gb1 = bits_classic(j1, HALF_G, ka, kb); gb2 = bits_classic(j1 + 32u, HALF_G, ka, kb); }
    else           { gb1 = bits_part(j1, ka, kb);            gb2 = bits_part(j1 + 32u, ka, kb); }
    float sc1 = logf(gam1) + gumbel_from_bits(gb1);
    float sc2 = logf(gam2) + gumbel_from_bits(gb2);

    float best; int bidx;
    if (sc2 > sc1) { best = sc2; bidx = lane + 32; }
    else           { best = sc1; bidx = lane; }
#pragma unroll
    for (int o = 16; o; o >>= 1) {
        float ob = __shfl_xor_sync(0xffffffffu, best, o);
        int   oi = __shfl_xor_sync(0xffffffffu, bidx, o);
        if (ob > best || (ob == best && oi < bidx)) { best = ob; bidx = oi; }
    }

    // eps ~ Normal over shape (2048,64,1); flat index = warp
    uint32_t p = (uint32_t)warp;
    uint32_t nbits;
    if (mode == 0) nbits = bits_classic(p, 65536u, na, nb);
    else           nbits = bits_part(p, na, nb);
    float eps = normal_from_bits(nbits);

    float sig_c = expf(y[64 + bidx]);
    float xp = fmaf(sig_c, eps, y[128 + bidx]);

    // mixture kernels (replicating reference fp32 op order)
    float prob;
    {
        float mu = y[128 + lane], ys = y[64 + lane];
        float d = xp - mu;
        float e = expf(-0.5f * (d * d));
        float sg = expf(ys);
        float k = e / (sg * sg);
        k = k / (C32 * expf(64.0f * ys));
        prob = gam1 * k;
    }
    {
        float mu = y[160 + lane], ys = y[96 + lane];
        float d = xp - mu;
        float e = expf(-0.5f * (d * d));
        float sg = expf(ys);
        float k = e / (sg * sg);
        k = k / (C32 * expf(64.0f * ys));
        prob += gam2 * k;
    }
#pragma unroll
    for (int o = 16; o; o >>= 1) prob += __shfl_xor_sync(0xffffffffu, prob, o);

    if (lane == 0) {
        out[warp] = xp;
        out[NPOS + warp] = prob;
    }
}

// ---------------- launch --------------------------------------------------------
extern "C" void kernel_launch(void* const* d_in, const int* in_sizes, int n_in,
                              void* d_out, int out_size)
{
    (void)in_sizes; (void)n_in; (void)out_size;
    const float* z    = (const float*)d_in[0];
    const float* Wih0 = (const float*)d_in[1];
    const float* Whh0 = (const float*)d_in[2];
    const float* bih0 = (const float*)d_in[3];
    const float* bhh0 = (const float*)d_in[4];
    const float* Wih1 = (const float*)d_in[5];
    const float* Whh1 = (const float*)d_in[6];
    const float* bih1 = (const float*)d_in[7];
    const float* bhh1 = (const float*)d_in[8];
    const float* fcW  = (const float*)d_in[9];
    const float* fcb  = (const float*)d_in[10];
    float* outp = (float*)d_out;

    // --- detection candidates for ks[0] of split(key(0), 12) ---
    // classic: ks[0] = (o0 of tf(0,0;0,12), o0 of tf(0,0;1,13))
    uint32_t ca, cb, pa, pb, dump;
    tf2x32(0u, 0u, 0u, 12u, ca, dump);
    tf2x32(0u, 0u, 1u, 13u, cb, dump);
    // partitionable: ks[0] = outputs of tf(0,0; 0,0)
    tf2x32(0u, 0u, 0u, 0u, pa, pb);

    // --- sampling keys: k1, k2 = split(key(42), 2) under each scheme ---
    // classic: k1 = (o0(0,2), o0(1,3)); k2 = (o1(0,2), o1(1,3))
    uint32_t p0o0, p0o1, p1o0, p1o1;
    tf2x32(0u, 42u, 0u, 2u, p0o0, p0o1);
    tf2x32(0u, 42u, 1u, 3u, p1o0, p1o1);
    uint32_t k1ca = p0o0, k1cb = p1o0;
    uint32_t k2ca = p0o1, k2cb = p1o1;
    // partitionable foldlike: k1 = tf(0,42; 0,0) outputs; k2 = tf(0,42; 0,1) outputs
    uint32_t s1a, s1b, s2a, s2b;
    tf2x32(0u, 42u, 0u, 0u, s1a, s1b);
    tf2x32(0u, 42u, 0u, 1u, s2a, s2b);

    float C32 = (float)pow(2.0 * M_PI, 32.0);

    dim3 ggrid(G_DIM / 128, M_BATCH / 64);   // (8, 32) = 256 blocks

    detect_mode<<<1, 32>>>(z, ca, cb, pa, pb);

    // layer 0
    zero_hc<<<(M_BATCH * H_DIM + 255) / 256, 256>>>();
    for (int t = 0; t < T_SEQ; t++) {
        gates_gemm<<<ggrid, 256>>>(z, IN_F, t, Wih0, Whh0, bih0, bhh0);
        lstm_point<<<(M_BATCH * H_DIM / 4) / 256, 256>>>(t);
    }
    // layer 1 (reads g_Hbuf, rewrites it in place per step)
    zero_hc<<<(M_BATCH * H_DIM + 255) / 256, 256>>>();
    for (int t = 0; t < T_SEQ; t++) {
        gates_gemm<<<ggrid, 256>>>(z /*unused*/, H_DIM, t, Wih1, Whh1, bih1, bhh1);
        lstm_point<<<(M_BATCH * H_DIM / 4) / 256, 256>>>(t);
    }
    // FC
    fc_gemm<<<dim3(OUT_DIM / 64, NPOS / 64), 256>>>(fcW, fcb);
    // MDN + sampling + density
    mdn_kernel<<<NPOS / 8, 256>>>(outp,
                                  k1ca, k1cb, k2ca, k2cb,
                                  s1a, s1b, s2a, s2b,
                                  C32);
}

// round 14
// speedup vs baseline: 1.2688x; 1.2688x over previous
#include <cuda_runtime.h>
#include <cstdint>
#include <math.h>

#define M_BATCH 2048
#define T_SEQ   64
#define IN_F    16
#define H_DIM   256
#define G_DIM   1024
#define NCOMP   64
#define OUT_DIM 192
#define NPOS    (M_BATCH * T_SEQ)   // 131072

// ---------------- scratch (device globals; no runtime allocation) -------------
__device__ float g_Hbuf[(size_t)NPOS * H_DIM];     // 134 MB: layer-0 h (all steps)
__device__ float g_Hbuf2[(size_t)NPOS * H_DIM];    // 134 MB: layer-1 h (all steps)
__device__ float g_c[M_BATCH * H_DIM];             // 2 MB (reused by both layers)
__device__ float g_y[(size_t)NPOS * OUT_DIM];      // 100 MB
__device__ int   g_mode;                           // PRNG scheme: 0=classic, 1=part, 2=part-swapped

// ---------------- JAX threefry2x32 (20 rounds) --------------------------------
__host__ __device__ __forceinline__ void tf2x32(uint32_t k0, uint32_t k1,
                                                uint32_t x0, uint32_t x1,
                                                uint32_t &o0, uint32_t &o1)
{
    uint32_t ks2 = k0 ^ k1 ^ 0x1BD11BDAu;
    x0 += k0; x1 += k1;
#define TF_R(r) { x0 += x1; x1 = (x1 << (r)) | (x1 >> (32 - (r))); x1 ^= x0; }
    TF_R(13) TF_R(15) TF_R(26) TF_R(6)
    x0 += k1;  x1 += ks2 + 1u;
    TF_R(17) TF_R(29) TF_R(16) TF_R(24)
    x0 += ks2; x1 += k0 + 2u;
    TF_R(13) TF_R(15) TF_R(26) TF_R(6)
    x0 += k0;  x1 += k1 + 3u;
    TF_R(17) TF_R(29) TF_R(16) TF_R(24)
    x0 += k1;  x1 += ks2 + 4u;
    TF_R(13) TF_R(15) TF_R(26) TF_R(6)
    x0 += ks2; x1 += k0 + 5u;
#undef TF_R
    o0 = x0; o1 = x1;
}

// classic JAX random_bits: odd/even half pairing over a draw of 2*half elements
__device__ __forceinline__ uint32_t bits_classic(uint32_t j, uint32_t half,
                                                 uint32_t ka, uint32_t kb) {
    uint32_t o0, o1;
    if (j < half) { tf2x32(ka, kb, j, j + half, o0, o1); return o0; }
    else          { tf2x32(ka, kb, j - half, j, o0, o1); return o1; }
}

// partitionable JAX random_bits (32-bit): counter = (hi=0, lo=j), fold = out0^out1
__device__ __forceinline__ uint32_t bits_part(uint32_t j, uint32_t ka, uint32_t kb) {
    uint32_t o0, o1;
    tf2x32(ka, kb, 0u, j, o0, o1);
    return o0 ^ o1;
}

// bits -> [0,1) float, JAX style
__device__ __forceinline__ float bits_to_unit(uint32_t bits) {
    return __uint_as_float((bits >> 9) | 0x3f800000u) - 1.0f;
}

// XLA ErfInv f32 (Giles polynomial)
__device__ __forceinline__ float erfinv32(float x) {
    float w = -log1pf(-x * x);
    float p;
    if (w < 5.0f) {
        w = w - 2.5f;
        p = 2.81022636e-08f;
        p = fmaf(p, w, 3.43273939e-07f);
        p = fmaf(p, w, -3.5233877e-06f);
        p = fmaf(p, w, -4.39150654e-06f);
        p = fmaf(p, w, 0.00021858087f);
        p = fmaf(p, w, -0.00125372503f);
        p = fmaf(p, w, -0.00417768164f);
        p = fmaf(p, w, 0.246640727f);
        p = fmaf(p, w, 1.50140941f);
    } else {
        w = sqrtf(w) - 3.0f;
        p = -0.000200214257f;
        p = fmaf(p, w, 0.000100950558f);
        p = fmaf(p, w, 0.00134934322f);
        p = fmaf(p, w, -0.00367342844f);
        p = fmaf(p, w, 0.00573950773f);
        p = fmaf(p, w, -0.0076224613f);
        p = fmaf(p, w, 0.00943887047f);
        p = fmaf(p, w, 1.00167406f);
        p = fmaf(p, w, 2.83297682f);
    }
    return p * x;
}

// standard normal from raw threefry bits (JAX: uniform(-0.99999994, 1) -> sqrt2*erfinv)
__device__ __forceinline__ float normal_from_bits(uint32_t bits) {
    float f = bits_to_unit(bits);
    float u = fmaxf(-0.99999994f, fmaf(f, 1.99999994f, -0.99999994f));
    return 1.41421356f * erfinv32(u);
}

// Gumbel from raw bits: -log(-log(uniform(tiny,1)))
__device__ __forceinline__ float gumbel_from_bits(uint32_t bits) {
    float f = bits_to_unit(bits);
    float u = fmaxf(1.17549435e-38f, f);
    return -logf(-logf(u));
}

// XLA/Eigen f32 tanh rational approximation
__device__ __forceinline__ float tanh_xla(float x) {
    float ax = fabsf(x);
    if (ax < 0.0004f) return x;
    float xc = fminf(fmaxf(x, -7.90531110763549805f), 7.90531110763549805f);
    float x2 = xc * xc;
    float p = -2.76076847742355e-16f;
    p = fmaf(p, x2, 2.00018790482477e-13f);
    p = fmaf(p, x2, -8.60467152213735e-11f);
    p = fmaf(p, x2, 5.12229709037114e-08f);
    p = fmaf(p, x2, 1.48572235717979e-05f);
    p = fmaf(p, x2, 6.37261928875436e-04f);
    p = fmaf(p, x2, 4.89352455891786e-03f);
    p = xc * p;
    float q = 1.19825839466702e-06f;
    q = fmaf(q, x2, 1.18534705686654e-04f);
    q = fmaf(q, x2, 2.26843463243900e-03f);
    q = fmaf(q, x2, 4.89352518554385e-03f);
    return p / q;
}

__device__ __forceinline__ float sigm(float x) {   // XLA logistic expansion
    return fmaf(0.5f, tanh_xla(0.5f * x), 0.5f);
}

// ---------------- PRNG scheme detection ----------------------------------------
// setup_inputs used key(0): ks = split(key(0), 12); z = normal(ks[0], (2048,64,16)).
// Predict z[0..4) under each candidate scheme; pick the closest. Pure function of
// the input data -> deterministic across calls.
__global__ void detect_mode(const float* __restrict__ z,
                            uint32_t ca, uint32_t cb,    // ks[0] classic
                            uint32_t pa, uint32_t pb)    // tf(0,0;0,0) outputs (o0,o1)
{
    if (threadIdx.x != 0 || blockIdx.x != 0) return;
    const uint32_t HALF_Z = 1048576u;  // 2048*64*16 / 2
    float d0 = 0.0f, d1 = 0.0f, d2 = 0.0f;
    for (uint32_t j = 0; j < 4; j++) {
        float zc = normal_from_bits(bits_classic(j, HALF_Z, ca, cb));
        float z1 = normal_from_bits(bits_part(j, pa, pb));   // key stacked (o0,o1)
        float z2 = normal_from_bits(bits_part(j, pb, pa));   // key stacked (o1,o0)
        float za = z[j];
        d0 += fabsf(za - zc);
        d1 += fabsf(za - z1);
        d2 += fabsf(za - z2);
    }
    int m = 0; float dbest = d0;
    if (d1 < dbest) { m = 1; dbest = d1; }
    if (d2 < dbest) { m = 2; }
    g_mode = m;
}

// ---------------- fused LSTM step: GEMM + bias + pointwise ----------------------
// Tile: BM=128 rows x BN=128 gate-columns covering 32 h-indices * 4 gates.
// Column cn maps to gate = cn&3, h = h0 + (cn>>2). Each thread (tx,ty) owns
// 8 rows x 8 cols = 8 m * (2 h * 4 gates) -> full (i,f,g,o) per (m,h) pair.
// Epilogue applies the LSTM recurrence in-register:
//   c' = sigm(f)*c + sigm(i)*tanh(g);  h' = sigm(o)*tanh(c')
// h-prev is read from the OUTPUT buffer at step t-1 (zero at t==0);
// layer 0: x=z, h-buf=g_Hbuf;  layer 1: x=g_Hbuf, h-buf=g_Hbuf2 (no in-place race).
// Per-element k-summation order identical to the R13-passing kernel.
__global__ void lstm_step_fused(int layer, int t, const float* __restrict__ z,
                                const float* __restrict__ Wih,
                                const float* __restrict__ Whh,
                                const float* __restrict__ bih,
                                const float* __restrict__ bhh)
{
    __shared__ float As[16][132];
    __shared__ float Bs[16][132];

    const int F = (layer == 0) ? IN_F : H_DIM;
    const float* Xsrc = (layer == 0) ? z : g_Hbuf;
    const float* Hsrc = (layer == 0) ? g_Hbuf : g_Hbuf2;
    float*       Hdst = (layer == 0) ? g_Hbuf : g_Hbuf2;

    int tid = threadIdx.x;
    int m0 = blockIdx.y * 128;
    int h0 = blockIdx.x * 32;
    int tx = tid & 15, ty = tid >> 4;

    float acc[8][8];
#pragma unroll
    for (int r = 0; r < 8; r++)
#pragma unroll
        for (int c = 0; c < 8; c++) acc[r][c] = 0.0f;

    int K = F + H_DIM;
    for (int k0 = 0; k0 < K; k0 += 16) {
        bool isX = (k0 < F);
        // A tile (128 m x 16 k), transposed into As[k][m]: 2 float4/thread
#pragma unroll
        for (int i = 0; i < 2; i++) {
            int idx = tid + i * 256;
            int ml = idx >> 2;
            int c4 = (idx & 3) * 4;
            int mg = m0 + ml;
            float4 v;
            if (isX) {
                v = *reinterpret_cast<const float4*>(Xsrc + ((size_t)mg * T_SEQ + t) * F + (k0 + c4));
            } else if (t > 0) {
                v = *reinterpret_cast<const float4*>(Hsrc + ((size_t)mg * T_SEQ + (t - 1)) * H_DIM + (k0 - F + c4));
            } else {
                v = make_float4(0.0f, 0.0f, 0.0f, 0.0f);
            }
            As[c4 + 0][ml] = v.x; As[c4 + 1][ml] = v.y; As[c4 + 2][ml] = v.z; As[c4 + 3][ml] = v.w;
        }
        // B tile (128 gate-cols x 16 k): column nl -> weight row (nl&3)*256 + h0 + (nl>>2)
#pragma unroll
        for (int i = 0; i < 2; i++) {
            int idx = tid + i * 256;
            int nl = idx >> 2;
            int c4 = (idx & 3) * 4;
            int grow = (nl & 3) * H_DIM + h0 + (nl >> 2);
            float4 v;
            if (isX) v = *reinterpret_cast<const float4*>(Wih + (size_t)grow * F + (k0 + c4));
            else     v = *reinterpret_cast<const float4*>(Whh + (size_t)grow * H_DIM + (k0 - F + c4));
            Bs[c4 + 0][nl] = v.x; Bs[c4 + 1][nl] = v.y; Bs[c4 + 2][nl] = v.z; Bs[c4 + 3][nl] = v.w;
        }
        __syncthreads();
#pragma unroll
        for (int kk = 0; kk < 16; kk++) {
            float a[8], b[8];
            *reinterpret_cast<float4*>(&a[0]) = *reinterpret_cast<const float4*>(&As[kk][ty * 8]);
            *reinterpret_cast<float4*>(&a[4]) = *reinterpret_cast<const float4*>(&As[kk][ty * 8 + 4]);
            *reinterpret_cast<float4*>(&b[0]) = *reinterpret_cast<const float4*>(&Bs[kk][tx * 8]);
            *reinterpret_cast<float4*>(&b[4]) = *reinterpret_cast<const float4*>(&Bs[kk][tx * 8 + 4]);
#pragma unroll
            for (int r = 0; r < 8; r++)
#pragma unroll
                for (int c = 0; c < 8; c++) acc[r][c] = fmaf(a[r], b[c], acc[r][c]);
        }
        __syncthreads();
    }

    // epilogue: bias + LSTM pointwise, write c and h
    float bb[8];
#pragma unroll
    for (int c = 0; c < 8; c++) {
        int cn = tx * 8 + c;
        int grow = (cn & 3) * H_DIM + h0 + (cn >> 2);
        bb[c] = bih[grow] + bhh[grow];
    }
#pragma unroll
    for (int r = 0; r < 8; r++) {
        int m = m0 + ty * 8 + r;
#pragma unroll
        for (int p = 0; p < 2; p++) {
            float ig = acc[r][p * 4 + 0] + bb[p * 4 + 0];
            float fg = acc[r][p * 4 + 1] + bb[p * 4 + 1];
            float gg = acc[r][p * 4 + 2] + bb[p * 4 + 2];
            float og = acc[r][p * 4 + 3] + bb[p * 4 + 3];
            int h = h0 + tx * 2 + p;
            size_t ci = (size_t)m * H_DIM + h;
            float cv = (t > 0) ? g_c[ci] : 0.0f;
            cv = sigm(fg) * cv + sigm(ig) * tanh_xla(gg);
            float hv = sigm(og) * tanh_xla(cv);
            g_c[ci] = cv;
            Hdst[((size_t)m * T_SEQ + t) * H_DIM + h] = hv;
        }
    }
}

// ---------------- FC GEMM: y = H1 @ fcW^T + fcb (reads g_Hbuf2) ----------------
__global__ void fc_gemm(const float* __restrict__ fcW, const float* __restrict__ fcb) {
    __shared__ float As[16][68];
    __shared__ float Bs[16][68];
    int tid = threadIdx.x;
    int m0 = blockIdx.y * 64;
    int n0 = blockIdx.x * 64;
    int tx = tid & 15, ty = tid >> 4;
    float acc[4][4];
#pragma unroll
    for (int r = 0; r < 4; r++)
#pragma unroll
        for (int c = 0; c < 4; c++) acc[r][c] = 0.0f;

    for (int k0 = 0; k0 < H_DIM; k0 += 16) {
        {
            int ml = tid >> 2, c4 = (tid & 3) * 4;
            float4 v = *reinterpret_cast<const float4*>(g_Hbuf2 + (size_t)(m0 + ml) * H_DIM + k0 + c4);
            As[c4 + 0][ml] = v.x; As[c4 + 1][ml] = v.y; As[c4 + 2][ml] = v.z; As[c4 + 3][ml] = v.w;
        }
        {
            int nl = tid >> 2, c4 = (tid & 3) * 4;
            float4 v = *reinterpret_cast<const float4*>(fcW + (size_t)(n0 + nl) * H_DIM + k0 + c4);
            Bs[c4 + 0][nl] = v.x; Bs[c4 + 1][nl] = v.y; Bs[c4 + 2][nl] = v.z; Bs[c4 + 3][nl] = v.w;
        }
        __syncthreads();
#pragma unroll
        for (int kk = 0; kk < 16; kk++) {
            float a[4], b[4];
            *reinterpret_cast<float4*>(a) = *reinterpret_cast<const float4*>(&As[kk][ty * 4]);
            *reinterpret_cast<float4*>(b) = *reinterpret_cast<const float4*>(&Bs[kk][tx * 4]);
#pragma unroll
            for (int r = 0; r < 4; r++)
#pragma unroll
                for (int c = 0; c < 4; c++) acc[r][c] = fmaf(a[r], b[c], acc[r][c]);
        }
        __syncthreads();
    }
#pragma unroll
    for (int r = 0; r < 4; r++) {
        int mg = m0 + ty * 4 + r;
        float* dst = g_y + (size_t)mg * OUT_DIM + n0 + tx * 4;
        float4 v = make_float4(acc[r][0] + fcb[n0 + tx * 4 + 0],
                               acc[r][1] + fcb[n0 + tx * 4 + 1],
                               acc[r][2] + fcb[n0 + tx * 4 + 2],
                               acc[r][3] + fcb[n0 + tx * 4 + 3]);
        *reinterpret_cast<float4*>(dst) = v;
    }
}

// ---------------- MDN head: softmax + Gumbel categorical + normal + prob ------
__global__ void mdn_kernel(float* __restrict__ out,
                           uint32_t k1ca, uint32_t k1cb, uint32_t k2ca, uint32_t k2cb,
                           uint32_t s1a,  uint32_t s1b,  uint32_t s2a,  uint32_t s2b,
                           float C32)
{
    int warp = (blockIdx.x * blockDim.x + threadIdx.x) >> 5;
    int lane = threadIdx.x & 31;
    if (warp >= NPOS) return;
    const float* y = g_y + (size_t)warp * OUT_DIM;

    int mode = g_mode;
    uint32_t ka, kb, na, nb;
    if (mode == 0)      { ka = k1ca; kb = k1cb; na = k2ca; nb = k2cb; }
    else if (mode == 1) { ka = s1a;  kb = s1b;  na = s2a;  nb = s2b;  }
    else                { ka = s1b;  kb = s1a;  na = s2b;  nb = s2a;  }

    float yg1 = y[lane], yg2 = y[lane + 32];
    float mx = fmaxf(yg1, yg2);
#pragma unroll
    for (int o = 16; o; o >>= 1) mx = fmaxf(mx, __shfl_xor_sync(0xffffffffu, mx, o));
    float e1 = expf(yg1 - mx), e2 = expf(yg2 - mx);
    float s = e1 + e2;
#pragma unroll
    for (int o = 16; o; o >>= 1) s += __shfl_xor_sync(0xffffffffu, s, o);
    float gam1 = e1 / s, gam2 = e2 / s;

    const uint32_t HALF_G = 4194304u;
    uint32_t j1 = (uint32_t)warp * 64u + (uint32_t)lane;
    uint32_t gb1, gb2;
    if (mode == 0) { gb1 = bits_classic(j1, HALF_G, ka, kb); gb2 = bits_classic(j1 + 32u, HALF_G, ka, kb); }
    else           { gb1 = bits_part(j1, ka, kb);            gb2 = bits_part(j1 + 32u, ka, kb); }
    float sc1 = logf(gam1) + gumbel_from_bits(gb1);
    float sc2 = logf(gam2) + gumbel_from_bits(gb2);

    float best; int bidx;
    if (sc2 > sc1) { best = sc2; bidx = lane + 32; }
    else           { best = sc1; bidx = lane; }
#pragma unroll
    for (int o = 16; o; o >>= 1) {
        float ob = __shfl_xor_sync(0xffffffffu, best, o);
        int   oi = __shfl_xor_sync(0xffffffffu, bidx, o);
        if (ob > best || (ob == best && oi < bidx)) { best = ob; bidx = oi; }
    }

    uint32_t p = (uint32_t)warp;
    uint32_t nbits;
    if (mode == 0) nbits = bits_classic(p, 65536u, na, nb);
    else           nbits = bits_part(p, na, nb);
    float eps = normal_from_bits(nbits);

    float sig_c = expf(y[64 + bidx]);
    float xp = fmaf(sig_c, eps, y[128 + bidx]);

    float prob;
    {
        float mu = y[128 + lane], ys = y[64 + lane];
        float d = xp - mu;
        float e = expf(-0.5f * (d * d));
        float sg = expf(ys);
        float k = e / (sg * sg);
        k = k / (C32 * expf(64.0f * ys));
        prob = gam1 * k;
    }
    {
        float mu = y[160 + lane], ys = y[96 + lane];
        float d = xp - mu;
        float e = expf(-0.5f * (d * d));
        float sg = expf(ys);
        float k = e / (sg * sg);
        k = k / (C32 * expf(64.0f * ys));
        prob += gam2 * k;
    }
#pragma unroll
    for (int o = 16; o; o >>= 1) prob += __shfl_xor_sync(0xffffffffu, prob, o);

    if (lane == 0) {
        out[warp] = xp;
        out[NPOS + warp] = prob;
    }
}

// ---------------- launch --------------------------------------------------------
extern "C" void kernel_launch(void* const* d_in, const int* in_sizes, int n_in,
                              void* d_out, int out_size)
{
    (void)in_sizes; (void)n_in; (void)out_size;
    const float* z    = (const float*)d_in[0];
    const float* Wih0 = (const float*)d_in[1];
    const float* Whh0 = (const float*)d_in[2];
    const float* bih0 = (const float*)d_in[3];
    const float* bhh0 = (const float*)d_in[4];
    const float* Wih1 = (const float*)d_in[5];
    const float* Whh1 = (const float*)d_in[6];
    const float* bih1 = (const float*)d_in[7];
    const float* bhh1 = (const float*)d_in[8];
    const float* fcW  = (const float*)d_in[9];
    const float* fcb  = (const float*)d_in[10];
    float* outp = (float*)d_out;

    // --- detection candidates for ks[0] of split(key(0), 12) ---
    uint32_t ca, cb, pa, pb, dump;
    tf2x32(0u, 0u, 0u, 12u, ca, dump);
    tf2x32(0u, 0u, 1u, 13u, cb, dump);
    tf2x32(0u, 0u, 0u, 0u, pa, pb);

    // --- sampling keys: k1, k2 = split(key(42), 2) under each scheme ---
    uint32_t p0o0, p0o1, p1o0, p1o1;
    tf2x32(0u, 42u, 0u, 2u, p0o0, p0o1);
    tf2x32(0u, 42u, 1u, 3u, p1o0, p1o1);
    uint32_t k1ca = p0o0, k1cb = p1o0;
    uint32_t k2ca = p0o1, k2cb = p1o1;
    uint32_t s1a, s1b, s2a, s2b;
    tf2x32(0u, 42u, 0u, 0u, s1a, s1b);
    tf2x32(0u, 42u, 0u, 1u, s2a, s2b);

    float C32 = (float)pow(2.0 * M_PI, 32.0);

    dim3 lgrid(H_DIM / 32, M_BATCH / 128);   // (8, 16) = 128 blocks

    detect_mode<<<1, 32>>>(z, ca, cb, pa, pb);

    // layer 0 (fused GEMM + pointwise; h -> g_Hbuf)
    for (int t = 0; t < T_SEQ; t++)
        lstm_step_fused<<<lgrid, 256>>>(0, t, z, Wih0, Whh0, bih0, bhh0);
    // layer 1 (x from g_Hbuf, h -> g_Hbuf2)
    for (int t = 0; t < T_SEQ; t++)
        lstm_step_fused<<<lgrid, 256>>>(1, t, z, Wih1, Whh1, bih1, bhh1);
    // FC
    fc_gemm<<<dim3(OUT_DIM / 64, NPOS / 64), 256>>>(fcW, fcb);
    // MDN + sampling + density
    mdn_kernel<<<NPOS / 8, 256>>>(outp,
                                  k1ca, k1cb, k2ca, k2cb,
                                  s1a, s1b, s2a, s2b,
                                  C32);
}